// round 10
// baseline (speedup 1.0000x reference)
#include <cuda_runtime.h>
#include <cuda_fp16.h>
#include <math.h>

#define NB 4
#define FB 32
#define HIN 1024
#define CIN 8
#define DD 64
#define WW 7
#define HO 1018
#define HP 1024
#define NSLICE (NB*FB)

// fp16 scratch (zero-initialized; padded rows of q1/q2 never written -> stay 0)
__device__ __half g_q1h[(size_t)NSLICE * HP * DD];
__device__ __half g_q2h[(size_t)NSLICE * HP * DD];
__device__ __half g_p1h[(size_t)NSLICE * HP * DD];

// ---------------------------------------------------------------------------
// helpers
// ---------------------------------------------------------------------------
__device__ __forceinline__ void mma16(float* d, const unsigned* a, unsigned b0, unsigned b1) {
    asm volatile(
        "mma.sync.aligned.m16n8k16.row.col.f32.f16.f16.f32 "
        "{%0,%1,%2,%3},{%4,%5,%6,%7},{%8,%9},{%0,%1,%2,%3};"
        : "+f"(d[0]), "+f"(d[1]), "+f"(d[2]), "+f"(d[3])
        : "r"(a[0]), "r"(a[1]), "r"(a[2]), "r"(a[3]), "r"(b0), "r"(b1));
}

__device__ __forceinline__ void ldsm4(unsigned* r, const void* p) {
    unsigned a = (unsigned)__cvta_generic_to_shared(p);
    asm volatile("ldmatrix.sync.aligned.m8n8.x4.shared.b16 {%0,%1,%2,%3},[%4];"
                 : "=r"(r[0]), "=r"(r[1]), "=r"(r[2]), "=r"(r[3]) : "r"(a));
}

__device__ __forceinline__ void ldsm4t(unsigned* r, const void* p) {
    unsigned a = (unsigned)__cvta_generic_to_shared(p);
    asm volatile("ldmatrix.sync.aligned.m8n8.x4.trans.shared.b16 {%0,%1,%2,%3},[%4];"
                 : "=r"(r[0]), "=r"(r[1]), "=r"(r[2]), "=r"(r[3]) : "r"(a));
}

__device__ __forceinline__ void cpa16(void* s, const void* g) {
    unsigned sa = (unsigned)__cvta_generic_to_shared(s);
    asm volatile("cp.async.cg.shared.global [%0],[%1],16;" :: "r"(sa), "l"(g));
}
#define CP_COMMIT asm volatile("cp.async.commit_group;")
#define CP_WAIT0  asm volatile("cp.async.wait_group 0;")

__device__ __forceinline__ unsigned h2u(float x, float y) {
    __half2 h = __float22half2_rn(make_float2(x, y));
    return *(unsigned*)&h;
}

// XOR swizzle for 128B rows of 64 halves: 16B unit u (0..7), phys = u ^ (row&7)
__device__ __forceinline__ int swz(int row, int u) {
    return row * 64 + ((u ^ (row & 7)) << 3);
}

// ---------------------------------------------------------------------------
// Projection: float4 d-quads, 8 h-rows/thread, transposed W in smem.
// CTA 256 thr = 16 hblk x 16 dquad -> 128 h rows. grid (8, F, 2N).
// ---------------------------------------------------------------------------
__global__ __launch_bounds__(256) void proj_kernel(const float* __restrict__ x1,
                                                   const float* __restrict__ x2,
                                                   const float* __restrict__ W)
{
    __shared__ float Wt[WW * CIN * DD];   // [j][c][d]
    const int f = blockIdx.y;
    const int which = blockIdx.z & 1, n = blockIdx.z >> 1;
    const float* Wf = W + (size_t)f * CIN * DD * WW;
    for (int i = threadIdx.x; i < CIN * DD * WW; i += 256) {
        int c = i / (DD * WW), rem = i - c * DD * WW;
        int d = rem / WW, j = rem - d * WW;
        Wt[(j * CIN + c) * DD + d] = Wf[i];
    }
    __syncthreads();

    const float* x = which ? x2 : x1;
    __half* q = which ? g_q2h : g_q1h;

    const int tid = threadIdx.x;
    const int d = (tid & 15) * 4;
    const int hb = tid >> 4;
    const int h0 = blockIdx.x * 128 + hb * 8;

    float4 acc[8];
#pragma unroll
    for (int i = 0; i < 8; i++) acc[i] = make_float4(0.f, 0.f, 0.f, 0.f);

#pragma unroll
    for (int c = 0; c < CIN; c++) {
        float4 xc[14];
#pragma unroll
        for (int i = 0; i < 14; i++) {
            int hr = h0 + i;
            hr = hr < HIN ? hr : HIN - 1;   // clamp; those outputs are discarded
            xc[i] = *(const float4*)(x + ((size_t)(n * HIN + hr) * CIN + c) * DD + d);
        }
#pragma unroll
        for (int j = 0; j < WW; j++) {
            float4 w = *(const float4*)&Wt[(j * CIN + c) * DD + d];
#pragma unroll
            for (int i = 0; i < 8; i++) {
                acc[i].x += xc[i + j].x * w.x;
                acc[i].y += xc[i + j].y * w.y;
                acc[i].z += xc[i + j].z * w.z;
                acc[i].w += xc[i + j].w * w.w;
            }
        }
    }

    __half* qb = q + ((size_t)(n * FB + f) * HP) * DD + d;
#pragma unroll
    for (int i = 0; i < 8; i++) {
        int h = h0 + i;
        if (h < HO) {
            __half2 lo = __floats2half2_rn(acc[i].x, acc[i].y);
            __half2 hi = __floats2half2_rn(acc[i].z, acc[i].w);
            *(uint2*)(qb + (size_t)h * DD) = make_uint2(*(unsigned*)&lo, *(unsigned*)&hi);
        }
    }
}

// ---------------------------------------------------------------------------
// Persistent per-slice fused kernel: both phases.
// grid = 128 CTAs (one slice each), 512 threads, 16 warps = 2 mw x 8 gw.
// smem: Vs (q2 resident, 1024x64 swz, 128KB) | Ss (2x128x64 stream, 32KB;
//       Obuf f32 8x32x32 overlays) | Q1s (2x32x64, 8KB) | red | lsm
// ---------------------------------------------------------------------------
#define SM_SS   131072
#define SM_Q1S  163840
#define SM_RED  172032
#define SM_LSM  173056
#define SMEM_F2 173184

__global__ __launch_bounds__(512, 1) void fused2_kernel(float* __restrict__ out)
{
    extern __shared__ __align__(16) char sm[];
    __half* Vs   = (__half*)sm;
    __half* Ss   = (__half*)(sm + SM_SS);
    float*  Obuf = (float*)(sm + SM_SS);     // overlays Ss (disjoint in time)
    __half* Q1s  = (__half*)(sm + SM_Q1S);
    float*  red  = (float*)(sm + SM_RED);
    float*  lsm  = (float*)(sm + SM_LSM);

    const int slice = blockIdx.x;
    const int tid = threadIdx.x;
    const int warp = tid >> 5, lane = tid & 31;
    const int gw = warp & 7, mw = warp >> 3;
    const int gq = lane >> 2, qi = lane & 3;
    const int nbt = slice >> 5, f = slice & 31;

    const __half* Vg  = g_q2h + (size_t)slice * HP * DD;
    const __half* Q1g = g_q1h + (size_t)slice * HP * DD;
    __half*       P1g = g_p1h + (size_t)slice * HP * DD;

    // ---- init: resident q2 slice + Q1 tile 0
#pragma unroll
    for (int r = 0; r < 16; r++) {
        int op = tid + r * 512, row = op >> 3, u = op & 7;
        cpa16(Vs + swz(row, u), Vg + (size_t)row * 64 + u * 8);
    }
    if (tid < 256) {
        int row = tid >> 3, u = tid & 7;
        cpa16(Q1s + swz(row, u), Q1g + (size_t)row * 64 + u * 8);
    }
    CP_COMMIT; CP_WAIT0; __syncthreads();

    for (int ph = 0; ph < 2; ph++) {
        float* outb = out + (size_t)ph * NB * HO * FB * DD;
#pragma unroll 1
        for (int b = 0; b < 32; b++) {
            const int h0 = b * 32;
            const __half* q1b = Q1s + (b & 1) * 2048;
            unsigned afr[4][4];
#pragma unroll
            for (int ks = 0; ks < 4; ks++)
                ldsm4(afr[ks], q1b + swz(mw * 16 + (lane & 15), ks * 2 + (lane >> 4)));

            // prefetch next Q1 tile (tile 0 again when crossing into phase 1)
            if (b < 31 || ph == 0) {
                int t = (b + 1) & 31;
                if (tid < 256) {
                    int row = tid >> 3, u = tid & 7;
                    cpa16(Q1s + ((b + 1) & 1) * 2048 + swz(row, u),
                          Q1g + ((size_t)(t * 32 + row)) * 64 + u * 8);
                }
                CP_COMMIT;
            }
            // phase 1: pre-issue p1 chunk 0 (overlaps the whole S-GEMM)
            if (ph == 1) {
#pragma unroll
                for (int r = 0; r < 2; r++) {
                    int op = tid + r * 512, rw = op >> 3, u = op & 7;
                    cpa16(Ss + swz(rw, u), P1g + (size_t)rw * 64 + u * 8);
                }
                CP_COMMIT;
            }

            // ---- S = Q1 * q2^T  (fully resident, no waits)
            float acc[16][4] = {};
#pragma unroll
            for (int c = 0; c < 8; c++) {
                unsigned bb[4][4];
#pragma unroll
                for (int ks = 0; ks < 4; ks++)
                    ldsm4(bb[ks], Vs + swz(c * 128 + gw * 16 + (lane & 15),
                                           ks * 2 + (lane >> 4)));
#pragma unroll
                for (int ks = 0; ks < 4; ks++) {
                    mma16(acc[c * 2],     afr[ks], bb[ks][0], bb[ks][2]);
                    mma16(acc[c * 2 + 1], afr[ks], bb[ks][1], bb[ks][3]);
                }
            }

            // ---- softmax (no max-shift; args bounded ~|3|)
            const float sc = 1.0f / 1018.0f;
            float l0 = 0.f, l1 = 0.f;
#pragma unroll
            for (int j = 0; j < 16; j++) {
                int gcol = (j >> 1) * 128 + gw * 16 + (j & 1) * 8 + 2 * qi;
                float e0 = (gcol < HO)     ? __expf(acc[j][0] * sc) : 0.f;
                float e1 = (gcol + 1 < HO) ? __expf(acc[j][1] * sc) : 0.f;
                float e2 = (gcol < HO)     ? __expf(acc[j][2] * sc) : 0.f;
                float e3 = (gcol + 1 < HO) ? __expf(acc[j][3] * sc) : 0.f;
                acc[j][0] = e0; acc[j][1] = e1; acc[j][2] = e2; acc[j][3] = e3;
                l0 += e0 + e1; l1 += e2 + e3;
            }
#pragma unroll
            for (int o = 1; o <= 2; o <<= 1) {
                l0 += __shfl_xor_sync(~0u, l0, o);
                l1 += __shfl_xor_sync(~0u, l1, o);
            }
            if (qi == 0) {
                red[gw * 32 + mw * 16 + gq] = l0;
                red[gw * 32 + mw * 16 + gq + 8] = l1;
            }
            __syncthreads();
            if (gw == 0 && qi == 0) {
                float L0 = 0.f, L1 = 0.f;
#pragma unroll
                for (int g2 = 0; g2 < 8; g2++) {
                    L0 += red[g2 * 32 + mw * 16 + gq];
                    L1 += red[g2 * 32 + mw * 16 + gq + 8];
                }
                lsm[mw * 16 + gq] = L0;
                lsm[mw * 16 + gq + 8] = L1;
            }

            // ---- O = P * V  (ph0: resident q2; ph1: streamed p1, double buffer)
            float od[8][4] = {};
#pragma unroll 1
            for (int c = 0; c < 8; c++) {
                if (ph == 1) {
                    CP_WAIT0; __syncthreads();     // chunk c landed; prev buf free
                    if (c < 7) {
#pragma unroll
                        for (int r = 0; r < 2; r++) {
                            int op = tid + r * 512, rw = op >> 3, u = op & 7;
                            cpa16(Ss + swz(((c + 1) & 1) * 128 + rw, u),
                                  P1g + ((size_t)((c + 1) * 128 + rw)) * 64 + u * 8);
                        }
                        CP_COMMIT;
                    }
                }
                unsigned a[4];
                a[0] = h2u(acc[c * 2][0],     acc[c * 2][1]);
                a[1] = h2u(acc[c * 2][2],     acc[c * 2][3]);
                a[2] = h2u(acc[c * 2 + 1][0], acc[c * 2 + 1][1]);
                a[3] = h2u(acc[c * 2 + 1][2], acc[c * 2 + 1][3]);
                const __half* vbase = ph ? Ss : Vs;
                const int rb = ph ? ((c & 1) * 128) : (c * 128);
#pragma unroll
                for (int dv = 0; dv < 4; dv++) {
                    unsigned bb[4];
                    ldsm4t(bb, vbase + swz(rb + gw * 16 + (lane & 15),
                                           dv * 2 + (lane >> 4)));
                    mma16(od[dv * 2],     a, bb[0], bb[1]);
                    mma16(od[dv * 2 + 1], a, bb[2], bb[3]);
                }
            }

            // ---- epilogue: cross-warp reduce over 8 g-groups, 2 rounds of 32 d
#pragma unroll
            for (int t = 0; t < 2; t++) {
                __syncthreads();
#pragma unroll
                for (int nf2 = 0; nf2 < 4; nf2++) {
                    int nf = t * 4 + nf2;
                    int row = mw * 16 + gq, dl = nf2 * 8 + 2 * qi;
                    *(float2*)&Obuf[(gw * 32 + row) * 32 + dl] =
                        make_float2(od[nf][0], od[nf][1]);
                    *(float2*)&Obuf[(gw * 32 + row + 8) * 32 + dl] =
                        make_float2(od[nf][2], od[nf][3]);
                }
                __syncthreads();
                {
                    int row = tid >> 4, dl = (tid & 15) * 2, dg = t * 32 + dl;
                    float inv = 1.0f / lsm[row];
                    float v0 = 0.f, v1 = 0.f;
#pragma unroll
                    for (int g2 = 0; g2 < 8; g2++) {
                        v0 += Obuf[(g2 * 32 + row) * 32 + dl];
                        v1 += Obuf[(g2 * 32 + row) * 32 + dl + 1];
                    }
                    v0 *= inv; v1 *= inv;
                    int h = h0 + row;
                    if (ph == 0)
                        *(__half2*)&P1g[(size_t)h * 64 + dg] = __floats2half2_rn(v0, v1);
                    if (h < HO)
                        *(float2*)&outb[((size_t)(nbt * HO + h) * FB + f) * DD + dg] =
                            make_float2(tanhf(v0), tanhf(v1));
                }
            }
            CP_WAIT0; __syncthreads();
        } // b
        if (ph == 0) { __threadfence(); __syncthreads(); }  // p1 -> L2 visible
    } // ph
}

// ---------------------------------------------------------------------------
extern "C" void kernel_launch(void* const* d_in, const int* in_sizes, int n_in,
                              void* d_out, int out_size)
{
    const float* prot1 = (const float*)d_in[0];
    const float* prot2 = (const float*)d_in[1];
    const float* W     = (const float*)d_in[2];
    float* out = (float*)d_out;

    cudaFuncSetAttribute(fused2_kernel, cudaFuncAttributeMaxDynamicSharedMemorySize,
                         SMEM_F2);

    proj_kernel<<<dim3(8, FB, 2 * NB), 256>>>(prot1, prot2, W);
    fused2_kernel<<<NSLICE, 512, SMEM_F2>>>(out);
}

// round 11
// speedup vs baseline: 1.0690x; 1.0690x over previous
#include <cuda_runtime.h>
#include <cuda_fp16.h>
#include <math.h>

#define NB 4
#define FB 32
#define HIN 1024
#define CIN 8
#define DD 64
#define WW 7
#define HO 1018
#define HP 1024
#define NSLICE (NB*FB)

// fp16 scratch (zero-initialized; padded rows of q1/q2 never written -> stay 0)
__device__ __half g_q1h[(size_t)NSLICE * HP * DD];
__device__ __half g_q2h[(size_t)NSLICE * HP * DD];
__device__ __half g_p1h[(size_t)NSLICE * HP * DD];

// ---------------------------------------------------------------------------
// helpers
// ---------------------------------------------------------------------------
__device__ __forceinline__ void mma16(float* d, const unsigned* a, unsigned b0, unsigned b1) {
    asm volatile(
        "mma.sync.aligned.m16n8k16.row.col.f32.f16.f16.f32 "
        "{%0,%1,%2,%3},{%4,%5,%6,%7},{%8,%9},{%0,%1,%2,%3};"
        : "+f"(d[0]), "+f"(d[1]), "+f"(d[2]), "+f"(d[3])
        : "r"(a[0]), "r"(a[1]), "r"(a[2]), "r"(a[3]), "r"(b0), "r"(b1));
}

__device__ __forceinline__ void ldsm4(unsigned* r, const void* p) {
    unsigned a = (unsigned)__cvta_generic_to_shared(p);
    asm volatile("ldmatrix.sync.aligned.m8n8.x4.shared.b16 {%0,%1,%2,%3},[%4];"
                 : "=r"(r[0]), "=r"(r[1]), "=r"(r[2]), "=r"(r[3]) : "r"(a));
}

__device__ __forceinline__ void ldsm4t(unsigned* r, const void* p) {
    unsigned a = (unsigned)__cvta_generic_to_shared(p);
    asm volatile("ldmatrix.sync.aligned.m8n8.x4.trans.shared.b16 {%0,%1,%2,%3},[%4];"
                 : "=r"(r[0]), "=r"(r[1]), "=r"(r[2]), "=r"(r[3]) : "r"(a));
}

__device__ __forceinline__ void cpa16(void* s, const void* g) {
    unsigned sa = (unsigned)__cvta_generic_to_shared(s);
    asm volatile("cp.async.cg.shared.global [%0],[%1],16;" :: "r"(sa), "l"(g));
}
#define CP_COMMIT asm volatile("cp.async.commit_group;")
#define CP_WAIT0  asm volatile("cp.async.wait_group 0;")

__device__ __forceinline__ void cp_wait_dyn(int n) {
    switch (n) {
        case 0: asm volatile("cp.async.wait_group 0;"); break;
        case 1: asm volatile("cp.async.wait_group 1;"); break;
        default: asm volatile("cp.async.wait_group 2;"); break;
    }
}

__device__ __forceinline__ unsigned h2u(float x, float y) {
    __half2 h = __float22half2_rn(make_float2(x, y));
    return *(unsigned*)&h;
}

// XOR swizzle for 128B rows of 64 halves: 16B unit u (0..7), phys = u ^ (row&7)
__device__ __forceinline__ int swz(int row, int u) {
    return row * 64 + ((u ^ (row & 7)) << 3);
}

// ---------------------------------------------------------------------------
// Projection: float4 d-quads, 8 h-rows/thread, transposed W in smem.
// CTA 256 thr = 16 hblk x 16 dquad -> 128 h rows. grid (8, F, 2N).
// ---------------------------------------------------------------------------
__global__ __launch_bounds__(256) void proj_kernel(const float* __restrict__ x1,
                                                   const float* __restrict__ x2,
                                                   const float* __restrict__ W)
{
    __shared__ float Wt[WW * CIN * DD];   // [j][c][d]
    const int f = blockIdx.y;
    const int which = blockIdx.z & 1, n = blockIdx.z >> 1;
    const float* Wf = W + (size_t)f * CIN * DD * WW;
    for (int i = threadIdx.x; i < CIN * DD * WW; i += 256) {
        int c = i / (DD * WW), rem = i - c * DD * WW;
        int d = rem / WW, j = rem - d * WW;
        Wt[(j * CIN + c) * DD + d] = Wf[i];
    }
    __syncthreads();

    const float* x = which ? x2 : x1;
    __half* q = which ? g_q2h : g_q1h;

    const int tid = threadIdx.x;
    const int d = (tid & 15) * 4;
    const int hb = tid >> 4;
    const int h0 = blockIdx.x * 128 + hb * 8;

    float4 acc[8];
#pragma unroll
    for (int i = 0; i < 8; i++) acc[i] = make_float4(0.f, 0.f, 0.f, 0.f);

#pragma unroll
    for (int c = 0; c < CIN; c++) {
        float4 xc[14];
#pragma unroll
        for (int i = 0; i < 14; i++) {
            int hr = h0 + i;
            hr = hr < HIN ? hr : HIN - 1;   // clamp; those outputs are discarded
            xc[i] = *(const float4*)(x + ((size_t)(n * HIN + hr) * CIN + c) * DD + d);
        }
#pragma unroll
        for (int j = 0; j < WW; j++) {
            float4 w = *(const float4*)&Wt[(j * CIN + c) * DD + d];
#pragma unroll
            for (int i = 0; i < 8; i++) {
                acc[i].x += xc[i + j].x * w.x;
                acc[i].y += xc[i + j].y * w.y;
                acc[i].z += xc[i + j].z * w.z;
                acc[i].w += xc[i + j].w * w.w;
            }
        }
    }

    __half* qb = q + ((size_t)(n * FB + f) * HP) * DD + d;
#pragma unroll
    for (int i = 0; i < 8; i++) {
        int h = h0 + i;
        if (h < HO) {
            __half2 lo = __floats2half2_rn(acc[i].x, acc[i].y);
            __half2 hi = __floats2half2_rn(acc[i].z, acc[i].w);
            *(uint2*)(qb + (size_t)h * DD) = make_uint2(*(unsigned*)&lo, *(unsigned*)&hi);
        }
    }
}

// ---------------------------------------------------------------------------
// Persistent per-slice fused kernel, both phases.
// grid = 128 CTAs, 512 threads, 16 warps = 2 mw x 8 gw.
// smem: Vs (q2 resident, 128KB) | Ss (4x16KB p1 stream; Obuf 64KB overlays)
//       | Q1s (2x32x64) | red | lsm
// Phase-1 p1 stream: depth-3 pipeline over the 4 Ss slots.
// ---------------------------------------------------------------------------
#define SM_SS   131072
#define SM_Q1S  196608
#define SM_RED  204800
#define SM_LSM  205824
#define SMEM_F2 205952

__global__ __launch_bounds__(512, 1) void fused2_kernel(float* __restrict__ out)
{
    extern __shared__ __align__(16) char sm[];
    __half* Vs   = (__half*)sm;
    __half* Ss   = (__half*)(sm + SM_SS);    // 4 slots x 8192 halves
    float*  Obuf = (float*)(sm + SM_SS);     // 64KB, overlays Ss (disjoint in time)
    __half* Q1s  = (__half*)(sm + SM_Q1S);
    float*  red  = (float*)(sm + SM_RED);
    float*  lsm  = (float*)(sm + SM_LSM);

    const int slice = blockIdx.x;
    const int tid = threadIdx.x;
    const int warp = tid >> 5, lane = tid & 31;
    const int gw = warp & 7, mw = warp >> 3;
    const int gq = lane >> 2, qi = lane & 3;
    const int nbt = slice >> 5, f = slice & 31;

    const __half* Vg  = g_q2h + (size_t)slice * HP * DD;
    const __half* Q1g = g_q1h + (size_t)slice * HP * DD;
    __half*       P1g = g_p1h + (size_t)slice * HP * DD;

    // ---- init: resident q2 slice + Q1 tile 0
#pragma unroll
    for (int r = 0; r < 16; r++) {
        int op = tid + r * 512, row = op >> 3, u = op & 7;
        cpa16(Vs + swz(row, u), Vg + (size_t)row * 64 + u * 8);
    }
    if (tid < 256) {
        int row = tid >> 3, u = tid & 7;
        cpa16(Q1s + swz(row, u), Q1g + (size_t)row * 64 + u * 8);
    }
    CP_COMMIT; CP_WAIT0; __syncthreads();

    for (int ph = 0; ph < 2; ph++) {
        float* outb = out + (size_t)ph * NB * HO * FB * DD;
#pragma unroll 1
        for (int b = 0; b < 32; b++) {
            const int h0 = b * 32;
            const __half* q1b = Q1s + (b & 1) * 2048;
            unsigned afr[4][4];
#pragma unroll
            for (int ks = 0; ks < 4; ks++)
                ldsm4(afr[ks], q1b + swz(mw * 16 + (lane & 15), ks * 2 + (lane >> 4)));

            // prefetch next Q1 tile (tile 0 again when crossing into phase 1)
            if (b < 31 || ph == 0) {
                int t = (b + 1) & 31;
                if (tid < 256) {
                    int row = tid >> 3, u = tid & 7;
                    cpa16(Q1s + ((b + 1) & 1) * 2048 + swz(row, u),
                          Q1g + ((size_t)(t * 32 + row)) * 64 + u * 8);
                }
                CP_COMMIT;
            }
            // phase 1: pre-issue p1 chunk 0 (overlaps the whole S-GEMM)
            if (ph == 1) {
#pragma unroll
                for (int r = 0; r < 2; r++) {
                    int op = tid + r * 512, rw = op >> 3, u = op & 7;
                    cpa16(Ss + swz(rw, u), P1g + (size_t)rw * 64 + u * 8);
                }
                CP_COMMIT;
            }

            // ---- S = Q1 * q2^T  (fully resident, no waits)
            float acc[16][4] = {};
#pragma unroll
            for (int c = 0; c < 8; c++) {
                unsigned bb[4][4];
#pragma unroll
                for (int ks = 0; ks < 4; ks++)
                    ldsm4(bb[ks], Vs + swz(c * 128 + gw * 16 + (lane & 15),
                                           ks * 2 + (lane >> 4)));
#pragma unroll
                for (int ks = 0; ks < 4; ks++) {
                    mma16(acc[c * 2],     afr[ks], bb[ks][0], bb[ks][2]);
                    mma16(acc[c * 2 + 1], afr[ks], bb[ks][1], bb[ks][3]);
                }
            }

            // phase 1: issue p1 chunks 1,2 (depth-3 pipeline established)
            if (ph == 1) {
#pragma unroll
                for (int nc = 1; nc <= 2; nc++) {
#pragma unroll
                    for (int r = 0; r < 2; r++) {
                        int op = tid + r * 512, rw = op >> 3, u = op & 7;
                        cpa16(Ss + nc * 8192 + swz(rw, u),
                              P1g + ((size_t)(nc * 128 + rw)) * 64 + u * 8);
                    }
                    CP_COMMIT;
                }
            }

            // ---- softmax (no max-shift; args bounded ~|3|)
            const float sc = 1.0f / 1018.0f;
            float l0 = 0.f, l1 = 0.f;
#pragma unroll
            for (int j = 0; j < 16; j++) {
                int gcol = (j >> 1) * 128 + gw * 16 + (j & 1) * 8 + 2 * qi;
                float e0 = (gcol < HO)     ? __expf(acc[j][0] * sc) : 0.f;
                float e1 = (gcol + 1 < HO) ? __expf(acc[j][1] * sc) : 0.f;
                float e2 = (gcol < HO)     ? __expf(acc[j][2] * sc) : 0.f;
                float e3 = (gcol + 1 < HO) ? __expf(acc[j][3] * sc) : 0.f;
                acc[j][0] = e0; acc[j][1] = e1; acc[j][2] = e2; acc[j][3] = e3;
                l0 += e0 + e1; l1 += e2 + e3;
            }
#pragma unroll
            for (int o = 1; o <= 2; o <<= 1) {
                l0 += __shfl_xor_sync(~0u, l0, o);
                l1 += __shfl_xor_sync(~0u, l1, o);
            }
            if (qi == 0) {
                red[gw * 32 + mw * 16 + gq] = l0;
                red[gw * 32 + mw * 16 + gq + 8] = l1;
            }
            __syncthreads();
            if (gw == 0 && qi == 0) {
                float L0 = 0.f, L1 = 0.f;
#pragma unroll
                for (int g2 = 0; g2 < 8; g2++) {
                    L0 += red[g2 * 32 + mw * 16 + gq];
                    L1 += red[g2 * 32 + mw * 16 + gq + 8];
                }
                lsm[mw * 16 + gq] = L0;
                lsm[mw * 16 + gq + 8] = L1;
            }

            // ---- O = P * V  (ph0: resident q2; ph1: p1 stream, depth-3/4-slot)
            float od[8][4] = {};
#pragma unroll 1
            for (int c = 0; c < 8; c++) {
                if (ph == 1) {
                    cp_wait_dyn(7 - c < 2 ? 7 - c : 2);  // chunk c landed
                    __syncthreads();                      // slot (c+3)&3 free
                    if (c + 3 <= 7) {
#pragma unroll
                        for (int r = 0; r < 2; r++) {
                            int op = tid + r * 512, rw = op >> 3, u = op & 7;
                            cpa16(Ss + ((c + 3) & 3) * 8192 + swz(rw, u),
                                  P1g + ((size_t)((c + 3) * 128 + rw)) * 64 + u * 8);
                        }
                        CP_COMMIT;
                    }
                }
                unsigned a[4];
                a[0] = h2u(acc[c * 2][0],     acc[c * 2][1]);
                a[1] = h2u(acc[c * 2][2],     acc[c * 2][3]);
                a[2] = h2u(acc[c * 2 + 1][0], acc[c * 2 + 1][1]);
                a[3] = h2u(acc[c * 2 + 1][2], acc[c * 2 + 1][3]);
                const __half* vbase = ph ? (Ss + (c & 3) * 8192) : (Vs + c * 128 * 64);
#pragma unroll
                for (int dv = 0; dv < 4; dv++) {
                    unsigned bb[4];
                    ldsm4t(bb, vbase + swz(gw * 16 + (lane & 15),
                                           dv * 2 + (lane >> 4)));
                    mma16(od[dv * 2],     a, bb[0], bb[1]);
                    mma16(od[dv * 2 + 1], a, bb[2], bb[3]);
                }
            }

            // ---- single-round epilogue: Obuf[8 gw][32 rows][64 d] overlays Ss
            __syncthreads();   // ph1: all streams drained at c=7 (wait 0)
#pragma unroll
            for (int nf = 0; nf < 8; nf++) {
                int row = mw * 16 + gq, dl = nf * 8 + 2 * qi;
                *(float2*)&Obuf[(gw * 32 + row) * 64 + dl] =
                    make_float2(od[nf][0], od[nf][1]);
                *(float2*)&Obuf[(gw * 32 + row + 8) * 64 + dl] =
                    make_float2(od[nf][2], od[nf][3]);
            }
            __syncthreads();
            {
                int row = tid >> 4, dg = (tid & 15) * 4;
                float inv = 1.0f / lsm[row];
                float v0 = 0.f, v1 = 0.f, v2 = 0.f, v3 = 0.f;
#pragma unroll
                for (int g2 = 0; g2 < 8; g2++) {
                    float4 p = *(const float4*)&Obuf[(g2 * 32 + row) * 64 + dg];
                    v0 += p.x; v1 += p.y; v2 += p.z; v3 += p.w;
                }
                v0 *= inv; v1 *= inv; v2 *= inv; v3 *= inv;
                int h = h0 + row;
                if (ph == 0) {
                    __half2 lo = __floats2half2_rn(v0, v1);
                    __half2 hi = __floats2half2_rn(v2, v3);
                    *(uint2*)&P1g[(size_t)h * 64 + dg] =
                        make_uint2(*(unsigned*)&lo, *(unsigned*)&hi);
                }
                if (h < HO)
                    *(float4*)&outb[((size_t)(nbt * HO + h) * FB + f) * DD + dg] =
                        make_float4(tanhf(v0), tanhf(v1), tanhf(v2), tanhf(v3));
            }
            __syncthreads();   // Obuf reads done before next b reuses Ss/Obuf
            CP_WAIT0;          // Q1 prefetch landed (ph0; ph1 already drained)
            __syncthreads();
        } // b
        if (ph == 0) { __threadfence(); __syncthreads(); }  // p1 -> L2 visible
    } // ph
}

// ---------------------------------------------------------------------------
extern "C" void kernel_launch(void* const* d_in, const int* in_sizes, int n_in,
                              void* d_out, int out_size)
{
    const float* prot1 = (const float*)d_in[0];
    const float* prot2 = (const float*)d_in[1];
    const float* W     = (const float*)d_in[2];
    float* out = (float*)d_out;

    cudaFuncSetAttribute(fused2_kernel, cudaFuncAttributeMaxDynamicSharedMemorySize,
                         SMEM_F2);

    proj_kernel<<<dim3(8, FB, 2 * NB), 256>>>(prot1, prot2, W);
    fused2_kernel<<<NSLICE, 512, SMEM_F2>>>(out);
}

// round 13
// speedup vs baseline: 2.6073x; 2.4390x over previous
#include <cuda_runtime.h>
#include <cuda_fp16.h>
#include <math.h>

#define NB 4
#define FB 32
#define HIN 1024
#define CIN 8
#define DD 64
#define WW 7
#define HO 1018
#define HP 1024
#define NSLICE (NB*FB)

// fp16 scratch (zero-initialized; padded rows of q1/q2 never written -> stay 0)
__device__ __half g_q1h[(size_t)NSLICE * HP * DD];
__device__ __half g_q2h[(size_t)NSLICE * HP * DD];
__device__ __half g_p1h[(size_t)NSLICE * HP * DD];

// ---------------------------------------------------------------------------
// helpers
// ---------------------------------------------------------------------------
__device__ __forceinline__ void mma16(float* d, const unsigned* a, unsigned b0, unsigned b1) {
    asm volatile(
        "mma.sync.aligned.m16n8k16.row.col.f32.f16.f16.f32 "
        "{%0,%1,%2,%3},{%4,%5,%6,%7},{%8,%9},{%0,%1,%2,%3};"
        : "+f"(d[0]), "+f"(d[1]), "+f"(d[2]), "+f"(d[3])
        : "r"(a[0]), "r"(a[1]), "r"(a[2]), "r"(a[3]), "r"(b0), "r"(b1));
}

__device__ __forceinline__ void ldsm4(unsigned* r, const void* p) {
    unsigned a = (unsigned)__cvta_generic_to_shared(p);
    asm volatile("ldmatrix.sync.aligned.m8n8.x4.shared.b16 {%0,%1,%2,%3},[%4];"
                 : "=r"(r[0]), "=r"(r[1]), "=r"(r[2]), "=r"(r[3]) : "r"(a));
}

__device__ __forceinline__ void ldsm4t(unsigned* r, const void* p) {
    unsigned a = (unsigned)__cvta_generic_to_shared(p);
    asm volatile("ldmatrix.sync.aligned.m8n8.x4.trans.shared.b16 {%0,%1,%2,%3},[%4];"
                 : "=r"(r[0]), "=r"(r[1]), "=r"(r[2]), "=r"(r[3]) : "r"(a));
}

__device__ __forceinline__ void cpa16(void* s, const void* g) {
    unsigned sa = (unsigned)__cvta_generic_to_shared(s);
    asm volatile("cp.async.cg.shared.global [%0],[%1],16;" :: "r"(sa), "l"(g));
}
#define CP_COMMIT asm volatile("cp.async.commit_group;")
#define CP_WAIT0  asm volatile("cp.async.wait_group 0;")
#define CP_WAIT1  asm volatile("cp.async.wait_group 1;")

__device__ __forceinline__ unsigned h2u(float x, float y) {
    __half2 h = __float22half2_rn(make_float2(x, y));
    return *(unsigned*)&h;
}

// XOR swizzle for 128B rows of 64 halves: 16B unit u (0..7), phys = u ^ (row&7)
__device__ __forceinline__ int swz(int row, int u) {
    return row * 64 + ((u ^ (row & 7)) << 3);
}

// ---------------------------------------------------------------------------
// Projection: float4 d-quads, 8 h-rows/thread, transposed W in smem.
// CTA 256 thr = 16 hblk x 16 dquad -> 128 h rows. grid (8, F, 2N).
// ---------------------------------------------------------------------------
__global__ __launch_bounds__(256) void proj_kernel(const float* __restrict__ x1,
                                                   const float* __restrict__ x2,
                                                   const float* __restrict__ W)
{
    __shared__ float Wt[WW * CIN * DD];   // [j][c][d]
    const int f = blockIdx.y;
    const int which = blockIdx.z & 1, n = blockIdx.z >> 1;
    const float* Wf = W + (size_t)f * CIN * DD * WW;
    for (int i = threadIdx.x; i < CIN * DD * WW; i += 256) {
        int c = i / (DD * WW), rem = i - c * DD * WW;
        int d = rem / WW, j = rem - d * WW;
        Wt[(j * CIN + c) * DD + d] = Wf[i];
    }
    __syncthreads();

    const float* x = which ? x2 : x1;
    __half* q = which ? g_q2h : g_q1h;

    const int tid = threadIdx.x;
    const int d = (tid & 15) * 4;
    const int hb = tid >> 4;
    const int h0 = blockIdx.x * 128 + hb * 8;

    float4 acc[8];
#pragma unroll
    for (int i = 0; i < 8; i++) acc[i] = make_float4(0.f, 0.f, 0.f, 0.f);

#pragma unroll
    for (int c = 0; c < CIN; c++) {
        float4 xc[14];
#pragma unroll
        for (int i = 0; i < 14; i++) {
            int hr = h0 + i;
            hr = hr < HIN ? hr : HIN - 1;   // clamp; those outputs are discarded
            xc[i] = *(const float4*)(x + ((size_t)(n * HIN + hr) * CIN + c) * DD + d);
        }
#pragma unroll
        for (int j = 0; j < WW; j++) {
            float4 w = *(const float4*)&Wt[(j * CIN + c) * DD + d];
#pragma unroll
            for (int i = 0; i < 8; i++) {
                acc[i].x += xc[i + j].x * w.x;
                acc[i].y += xc[i + j].y * w.y;
                acc[i].z += xc[i + j].z * w.z;
                acc[i].w += xc[i + j].w * w.w;
            }
        }
    }

    __half* qb = q + ((size_t)(n * FB + f) * HP) * DD + d;
#pragma unroll
    for (int i = 0; i < 8; i++) {
        int h = h0 + i;
        if (h < HO) {
            __half2 lo = __floats2half2_rn(acc[i].x, acc[i].y);
            __half2 hi = __floats2half2_rn(acc[i].z, acc[i].w);
            *(uint2*)(qb + (size_t)h * DD) = make_uint2(*(unsigned*)&lo, *(unsigned*)&hi);
        }
    }
}

// ---------------------------------------------------------------------------
// Fused pass, m-split (reduction-free). CTA = 128 h-rows, 8 warps x 16 rows.
// Loop over g in 16 blocks of 64; no max-shift => pure accumulation of
// l and O across g-blocks (no rescaling, no cross-warp reduce).
// smem: Q1s 128x64 (16KB) | Ks 2x(64x64) (16KB) | Vs 2x(64x64) (16KB, ph1)
// grid (8 h-blocks, 128 slices), 256 threads, 2 CTAs/SM.
// ---------------------------------------------------------------------------
__global__ __launch_bounds__(256, 2) void fused_kernel(float* __restrict__ out, int ph)
{
    __shared__ __align__(16) __half Q1s[128 * 64];
    __shared__ __align__(16) __half Ks[2 * 64 * 64];
    __shared__ __align__(16) __half Vs[2 * 64 * 64];

    const int slice = blockIdx.y;
    const int m0 = blockIdx.x * 128;
    const int tid = threadIdx.x;
    const int wid = tid >> 5, lane = tid & 31;
    const int gq = lane >> 2, qi = lane & 3;
    const int nbt = slice >> 5, f = slice & 31;

    const __half* Kg  = g_q2h + (size_t)slice * HP * DD;
    const __half* Vg  = (ph ? g_p1h : g_q2h) + (size_t)slice * HP * DD;
    const __half* Q1g = g_q1h + ((size_t)slice * HP + m0) * DD;
    __half*       P1g = g_p1h + (size_t)slice * HP * DD;

    // ---- prologue: G0 = Q1 + tile0, G1 = tile1
    {
#pragma unroll
        for (int r = 0; r < 4; r++) {
            int op = tid + r * 256, row = op >> 3, u = op & 7;
            cpa16(Q1s + swz(row, u), Q1g + (size_t)row * 64 + u * 8);
        }
#pragma unroll
        for (int r = 0; r < 2; r++) {
            int op = tid + r * 256, row = op >> 3, u = op & 7;
            cpa16(Ks + swz(row, u), Kg + (size_t)row * 64 + u * 8);
            if (ph) cpa16(Vs + swz(row, u), Vg + (size_t)row * 64 + u * 8);
        }
        CP_COMMIT;
#pragma unroll
        for (int r = 0; r < 2; r++) {
            int op = tid + r * 256, row = op >> 3, u = op & 7;
            cpa16(Ks + 4096 + swz(row, u), Kg + (size_t)(64 + row) * 64 + u * 8);
            if (ph) cpa16(Vs + 4096 + swz(row, u), Vg + (size_t)(64 + row) * 64 + u * 8);
        }
        CP_COMMIT;
    }

    // A fragments for this warp's 16 rows (reused across all g-blocks)
    CP_WAIT1; __syncthreads();
    unsigned afr[4][4];
#pragma unroll
    for (int ks = 0; ks < 4; ks++)
        ldsm4(afr[ks], Q1s + swz(wid * 16 + (lane & 15), ks * 2 + (lane >> 4)));

    const float sc = 1.0f / 1018.0f;
    float od[8][4] = {};
    float l0 = 0.f, l1 = 0.f;

#pragma unroll 1
    for (int kb = 0; kb < 16; kb++) {
        if (kb) { CP_WAIT1; __syncthreads(); }   // tile kb landed (kb=0 done above)
        const __half* Kt = Ks + (kb & 1) * 4096;
        const __half* Vt = ph ? (Vs + (kb & 1) * 4096) : Kt;

        // ---- S-frags: 16 rows x 64 g-cols of this block
        float acc[8][4] = {};
#pragma unroll
        for (int nb = 0; nb < 4; nb++) {
            unsigned bb[4][4];
#pragma unroll
            for (int ks = 0; ks < 4; ks++)
                ldsm4(bb[ks], Kt + swz(nb * 16 + (lane & 15), ks * 2 + (lane >> 4)));
#pragma unroll
            for (int ks = 0; ks < 4; ks++) {
                mma16(acc[nb * 2],     afr[ks], bb[ks][0], bb[ks][2]);
                mma16(acc[nb * 2 + 1], afr[ks], bb[ks][1], bb[ks][3]);
            }
        }

        // ---- exp (no max-shift); only kb=15 needs the g<HO mask
        if (kb < 15) {
#pragma unroll
            for (int j = 0; j < 8; j++) {
                acc[j][0] = __expf(acc[j][0] * sc);
                acc[j][1] = __expf(acc[j][1] * sc);
                acc[j][2] = __expf(acc[j][2] * sc);
                acc[j][3] = __expf(acc[j][3] * sc);
                l0 += acc[j][0] + acc[j][1];
                l1 += acc[j][2] + acc[j][3];
            }
        } else {
#pragma unroll
            for (int j = 0; j < 8; j++) {
                int gcol = kb * 64 + (j >> 1) * 16 + (j & 1) * 8 + 2 * qi;
                acc[j][0] = (gcol < HO)     ? __expf(acc[j][0] * sc) : 0.f;
                acc[j][1] = (gcol + 1 < HO) ? __expf(acc[j][1] * sc) : 0.f;
                acc[j][2] = (gcol < HO)     ? __expf(acc[j][2] * sc) : 0.f;
                acc[j][3] = (gcol + 1 < HO) ? __expf(acc[j][3] * sc) : 0.f;
                l0 += acc[j][0] + acc[j][1];
                l1 += acc[j][2] + acc[j][3];
            }
        }

        // ---- O += P * V over this block's 64 g (4 k16 steps)
#pragma unroll
        for (int kg = 0; kg < 4; kg++) {
            unsigned a[4];
            a[0] = h2u(acc[kg * 2][0],     acc[kg * 2][1]);
            a[1] = h2u(acc[kg * 2][2],     acc[kg * 2][3]);
            a[2] = h2u(acc[kg * 2 + 1][0], acc[kg * 2 + 1][1]);
            a[3] = h2u(acc[kg * 2 + 1][2], acc[kg * 2 + 1][3]);
#pragma unroll
            for (int dv = 0; dv < 4; dv++) {
                unsigned bb[4];
                ldsm4t(bb, Vt + swz(kg * 16 + (lane & 15), dv * 2 + (lane >> 4)));
                mma16(od[dv * 2],     a, bb[0], bb[1]);
                mma16(od[dv * 2 + 1], a, bb[2], bb[3]);
            }
        }

        // ---- free the slot we just read, then issue tile kb+2 into it
        __syncthreads();
        if (kb + 2 < 16) {
            int slot = kb & 1, g0 = (kb + 2) * 64;
#pragma unroll
            for (int r = 0; r < 2; r++) {
                int op = tid + r * 256, row = op >> 3, u = op & 7;
                cpa16(Ks + slot * 4096 + swz(row, u),
                      Kg + (size_t)(g0 + row) * 64 + u * 8);
                if (ph) cpa16(Vs + slot * 4096 + swz(row, u),
                              Vg + (size_t)(g0 + row) * 64 + u * 8);
            }
        }
        CP_COMMIT;   // uniform group counting (empty groups at the tail are fine)
    }

    // ---- epilogue: per-warp rows, no cross-warp traffic
    l0 += __shfl_xor_sync(~0u, l0, 1); l0 += __shfl_xor_sync(~0u, l0, 2);
    l1 += __shfl_xor_sync(~0u, l1, 1); l1 += __shfl_xor_sync(~0u, l1, 2);
    const float inv0 = 1.0f / l0, inv1 = 1.0f / l1;
    const int h0g = m0 + wid * 16;
    const int hA = h0g + gq, hB = h0g + gq + 8;

#pragma unroll
    for (int nf = 0; nf < 8; nf++) {
        int d = nf * 8 + 2 * qi;
        float vA0 = od[nf][0] * inv0, vA1 = od[nf][1] * inv0;
        float vB0 = od[nf][2] * inv1, vB1 = od[nf][3] * inv1;
        if (ph == 0) {
            *(__half2*)&P1g[(size_t)hA * DD + d] = __floats2half2_rn(vA0, vA1);
            *(__half2*)&P1g[(size_t)hB * DD + d] = __floats2half2_rn(vB0, vB1);
        }
        if (hA < HO)
            *(float2*)&out[((size_t)(nbt * HO + hA) * FB + f) * DD + d] =
                make_float2(tanhf(vA0), tanhf(vA1));
        if (hB < HO)
            *(float2*)&out[((size_t)(nbt * HO + hB) * FB + f) * DD + d] =
                make_float2(tanhf(vB0), tanhf(vB1));
    }
}

// ---------------------------------------------------------------------------
extern "C" void kernel_launch(void* const* d_in, const int* in_sizes, int n_in,
                              void* d_out, int out_size)
{
    const float* prot1 = (const float*)d_in[0];
    const float* prot2 = (const float*)d_in[1];
    const float* W     = (const float*)d_in[2];
    float* out = (float*)d_out;

    proj_kernel<<<dim3(8, FB, 2 * NB), 256>>>(prot1, prot2, W);
    fused_kernel<<<dim3(8, NSLICE), 256>>>(out, 0);
    fused_kernel<<<dim3(8, NSLICE), 256>>>(out + (size_t)NB * HO * FB * DD, 1);
}

// round 14
// speedup vs baseline: 2.7079x; 1.0386x over previous
#include <cuda_runtime.h>
#include <cuda_fp16.h>
#include <math.h>

#define NB 4
#define FB 32
#define HIN 1024
#define CIN 8
#define DD 64
#define WW 7
#define HO 1018
#define HP 1024
#define NSLICE (NB*FB)

// fp16 scratch (zero-initialized; padded rows of q1/q2 never written -> stay 0)
__device__ __half g_q1h[(size_t)NSLICE * HP * DD];
__device__ __half g_q2h[(size_t)NSLICE * HP * DD];
__device__ __half g_p1h[(size_t)NSLICE * HP * DD];

// ---------------------------------------------------------------------------
// helpers
// ---------------------------------------------------------------------------
__device__ __forceinline__ void mma16(float* d, const unsigned* a, unsigned b0, unsigned b1) {
    asm volatile(
        "mma.sync.aligned.m16n8k16.row.col.f32.f16.f16.f32 "
        "{%0,%1,%2,%3},{%4,%5,%6,%7},{%8,%9},{%0,%1,%2,%3};"
        : "+f"(d[0]), "+f"(d[1]), "+f"(d[2]), "+f"(d[3])
        : "r"(a[0]), "r"(a[1]), "r"(a[2]), "r"(a[3]), "r"(b0), "r"(b1));
}

__device__ __forceinline__ void ldsm4(unsigned* r, const void* p) {
    unsigned a = (unsigned)__cvta_generic_to_shared(p);
    asm volatile("ldmatrix.sync.aligned.m8n8.x4.shared.b16 {%0,%1,%2,%3},[%4];"
                 : "=r"(r[0]), "=r"(r[1]), "=r"(r[2]), "=r"(r[3]) : "r"(a));
}

__device__ __forceinline__ void ldsm4t(unsigned* r, const void* p) {
    unsigned a = (unsigned)__cvta_generic_to_shared(p);
    asm volatile("ldmatrix.sync.aligned.m8n8.x4.trans.shared.b16 {%0,%1,%2,%3},[%4];"
                 : "=r"(r[0]), "=r"(r[1]), "=r"(r[2]), "=r"(r[3]) : "r"(a));
}

__device__ __forceinline__ void cpa16(void* s, const void* g) {
    unsigned sa = (unsigned)__cvta_generic_to_shared(s);
    asm volatile("cp.async.cg.shared.global [%0],[%1],16;" :: "r"(sa), "l"(g));
}
#define CP_COMMIT asm volatile("cp.async.commit_group;")
#define CP_WAIT0  asm volatile("cp.async.wait_group 0;")
#define CP_WAIT1  asm volatile("cp.async.wait_group 1;")

__device__ __forceinline__ unsigned h2u(float x, float y) {
    __half2 h = __float22half2_rn(make_float2(x, y));
    return *(unsigned*)&h;
}

// XOR swizzle for 128B rows of 64 halves: 16B unit u (0..7), phys = u ^ (row&7)
__device__ __forceinline__ int swz(int row, int u) {
    return row * 64 + ((u ^ (row & 7)) << 3);
}

// ---------------------------------------------------------------------------
// Projection on the packed fp32 pipe (fma.rn.f32x2 -> FFMA2).
// Thread = (h-block of 8 rows) x (d-pair held as one f32x2 register pair).
// CTA 256 thr = 8 hblk x 32 dpair -> 64 h rows. grid (16, F, 2N).
// ---------------------------------------------------------------------------
__global__ __launch_bounds__(256) void proj_kernel(const float* __restrict__ x1,
                                                   const float* __restrict__ x2,
                                                   const float* __restrict__ W)
{
    __shared__ float Wt[WW * CIN * DD];   // [j][c][d]
    const int f = blockIdx.y;
    const int which = blockIdx.z & 1, n = blockIdx.z >> 1;
    const float* Wf = W + (size_t)f * CIN * DD * WW;
    for (int i = threadIdx.x; i < CIN * DD * WW; i += 256) {
        int c = i / (DD * WW), rem = i - c * DD * WW;
        int d = rem / WW, j = rem - d * WW;
        Wt[(j * CIN + c) * DD + d] = Wf[i];
    }
    __syncthreads();

    const float* x = which ? x2 : x1;
    __half* q = which ? g_q2h : g_q1h;

    const int tid = threadIdx.x;
    const int d = (tid & 31) * 2;
    const int hb = tid >> 5;
    const int h0 = blockIdx.x * 64 + hb * 8;

    unsigned long long acc[8] = {};   // f32x2 lanes; 0 bits == (0.f, 0.f)

#pragma unroll
    for (int c = 0; c < CIN; c++) {
        unsigned long long xc[14];
#pragma unroll
        for (int i = 0; i < 14; i++) {
            int hr = h0 + i;
            hr = hr < HIN ? hr : HIN - 1;   // clamp; those outputs are discarded
            xc[i] = *(const unsigned long long*)
                        (x + ((size_t)(n * HIN + hr) * CIN + c) * DD + d);
        }
#pragma unroll
        for (int j = 0; j < WW; j++) {
            float2 wv = *(const float2*)&Wt[(j * CIN + c) * DD + d];
            unsigned long long w01;
            asm("mov.b64 %0, {%1, %2};" : "=l"(w01) : "f"(wv.x), "f"(wv.y));
#pragma unroll
            for (int i = 0; i < 8; i++)
                asm("fma.rn.f32x2 %0, %1, %2, %0;"
                    : "+l"(acc[i]) : "l"(xc[i + j]), "l"(w01));
        }
    }

    __half* qb = q + ((size_t)(n * FB + f) * HP) * DD + d;
#pragma unroll
    for (int i = 0; i < 8; i++) {
        int h = h0 + i;
        if (h < HO) {
            float a0, a1;
            asm("mov.b64 {%0, %1}, %2;" : "=f"(a0), "=f"(a1) : "l"(acc[i]));
            *(__half2*)(qb + (size_t)h * DD) = __floats2half2_rn(a0, a1);
        }
    }
}

// ---------------------------------------------------------------------------
// Fused pass, m-split (reduction-free). CTA = 128 h-rows, 8 warps x 16 rows.
// Loop over g in 16 blocks of 64; no max-shift => pure accumulation of
// l and O across g-blocks (no rescaling, no cross-warp reduce).
// smem: Q1s 128x64 (16KB) | Ks 2x(64x64) (16KB) | Vs 2x(64x64) (16KB, ph1)
// grid (8 h-blocks, 128 slices), 256 threads, 2 CTAs/SM.
// ---------------------------------------------------------------------------
__global__ __launch_bounds__(256, 2) void fused_kernel(float* __restrict__ out, int ph)
{
    __shared__ __align__(16) __half Q1s[128 * 64];
    __shared__ __align__(16) __half Ks[2 * 64 * 64];
    __shared__ __align__(16) __half Vs[2 * 64 * 64];

    const int slice = blockIdx.y;
    const int m0 = blockIdx.x * 128;
    const int tid = threadIdx.x;
    const int wid = tid >> 5, lane = tid & 31;
    const int gq = lane >> 2, qi = lane & 3;
    const int nbt = slice >> 5, f = slice & 31;

    const __half* Kg  = g_q2h + (size_t)slice * HP * DD;
    const __half* Vg  = (ph ? g_p1h : g_q2h) + (size_t)slice * HP * DD;
    const __half* Q1g = g_q1h + ((size_t)slice * HP + m0) * DD;
    __half*       P1g = g_p1h + (size_t)slice * HP * DD;

    // ---- prologue: G0 = Q1 + tile0, G1 = tile1
    {
#pragma unroll
        for (int r = 0; r < 4; r++) {
            int op = tid + r * 256, row = op >> 3, u = op & 7;
            cpa16(Q1s + swz(row, u), Q1g + (size_t)row * 64 + u * 8);
        }
#pragma unroll
        for (int r = 0; r < 2; r++) {
            int op = tid + r * 256, row = op >> 3, u = op & 7;
            cpa16(Ks + swz(row, u), Kg + (size_t)row * 64 + u * 8);
            if (ph) cpa16(Vs + swz(row, u), Vg + (size_t)row * 64 + u * 8);
        }
        CP_COMMIT;
#pragma unroll
        for (int r = 0; r < 2; r++) {
            int op = tid + r * 256, row = op >> 3, u = op & 7;
            cpa16(Ks + 4096 + swz(row, u), Kg + (size_t)(64 + row) * 64 + u * 8);
            if (ph) cpa16(Vs + 4096 + swz(row, u), Vg + (size_t)(64 + row) * 64 + u * 8);
        }
        CP_COMMIT;
    }

    // A fragments for this warp's 16 rows (reused across all g-blocks)
    CP_WAIT1; __syncthreads();
    unsigned afr[4][4];
#pragma unroll
    for (int ks = 0; ks < 4; ks++)
        ldsm4(afr[ks], Q1s + swz(wid * 16 + (lane & 15), ks * 2 + (lane >> 4)));

    const float sc = 1.0f / 1018.0f;
    float od[8][4] = {};
    float l0 = 0.f, l1 = 0.f;

#pragma unroll 1
    for (int kb = 0; kb < 16; kb++) {
        if (kb) { CP_WAIT1; __syncthreads(); }   // tile kb landed (kb=0 done above)
        const __half* Kt = Ks + (kb & 1) * 4096;
        const __half* Vt = ph ? (Vs + (kb & 1) * 4096) : Kt;

        // ---- S-frags: 16 rows x 64 g-cols of this block
        float acc[8][4] = {};
#pragma unroll
        for (int nb = 0; nb < 4; nb++) {
            unsigned bb[4][4];
#pragma unroll
            for (int ks = 0; ks < 4; ks++)
                ldsm4(bb[ks], Kt + swz(nb * 16 + (lane & 15), ks * 2 + (lane >> 4)));
#pragma unroll
            for (int ks = 0; ks < 4; ks++) {
                mma16(acc[nb * 2],     afr[ks], bb[ks][0], bb[ks][2]);
                mma16(acc[nb * 2 + 1], afr[ks], bb[ks][1], bb[ks][3]);
            }
        }

        // ---- exp (no max-shift); only kb=15 needs the g<HO mask
        if (kb < 15) {
#pragma unroll
            for (int j = 0; j < 8; j++) {
                acc[j][0] = __expf(acc[j][0] * sc);
                acc[j][1] = __expf(acc[j][1] * sc);
                acc[j][2] = __expf(acc[j][2] * sc);
                acc[j][3] = __expf(acc[j][3] * sc);
                l0 += acc[j][0] + acc[j][1];
                l1 += acc[j][2] + acc[j][3];
            }
        } else {
#pragma unroll
            for (int j = 0; j < 8; j++) {
                int gcol = kb * 64 + (j >> 1) * 16 + (j & 1) * 8 + 2 * qi;
                acc[j][0] = (gcol < HO)     ? __expf(acc[j][0] * sc) : 0.f;
                acc[j][1] = (gcol + 1 < HO) ? __expf(acc[j][1] * sc) : 0.f;
                acc[j][2] = (gcol < HO)     ? __expf(acc[j][2] * sc) : 0.f;
                acc[j][3] = (gcol + 1 < HO) ? __expf(acc[j][3] * sc) : 0.f;
                l0 += acc[j][0] + acc[j][1];
                l1 += acc[j][2] + acc[j][3];
            }
        }

        // ---- O += P * V over this block's 64 g (4 k16 steps)
#pragma unroll
        for (int kg = 0; kg < 4; kg++) {
            unsigned a[4];
            a[0] = h2u(acc[kg * 2][0],     acc[kg * 2][1]);
            a[1] = h2u(acc[kg * 2][2],     acc[kg * 2][3]);
            a[2] = h2u(acc[kg * 2 + 1][0], acc[kg * 2 + 1][1]);
            a[3] = h2u(acc[kg * 2 + 1][2], acc[kg * 2 + 1][3]);
#pragma unroll
            for (int dv = 0; dv < 4; dv++) {
                unsigned bb[4];
                ldsm4t(bb, Vt + swz(kg * 16 + (lane & 15), dv * 2 + (lane >> 4)));
                mma16(od[dv * 2],     a, bb[0], bb[1]);
                mma16(od[dv * 2 + 1], a, bb[2], bb[3]);
            }
        }

        // ---- free the slot we just read, then issue tile kb+2 into it
        __syncthreads();
        if (kb + 2 < 16) {
            int slot = kb & 1, g0 = (kb + 2) * 64;
#pragma unroll
            for (int r = 0; r < 2; r++) {
                int op = tid + r * 256, row = op >> 3, u = op & 7;
                cpa16(Ks + slot * 4096 + swz(row, u),
                      Kg + (size_t)(g0 + row) * 64 + u * 8);
                if (ph) cpa16(Vs + slot * 4096 + swz(row, u),
                              Vg + (size_t)(g0 + row) * 64 + u * 8);
            }
        }
        CP_COMMIT;   // uniform group counting (empty groups at the tail are fine)
    }

    // ---- epilogue: per-warp rows, no cross-warp traffic
    l0 += __shfl_xor_sync(~0u, l0, 1); l0 += __shfl_xor_sync(~0u, l0, 2);
    l1 += __shfl_xor_sync(~0u, l1, 1); l1 += __shfl_xor_sync(~0u, l1, 2);
    const float inv0 = 1.0f / l0, inv1 = 1.0f / l1;
    const int h0g = m0 + wid * 16;
    const int hA = h0g + gq, hB = h0g + gq + 8;

#pragma unroll
    for (int nf = 0; nf < 8; nf++) {
        int d = nf * 8 + 2 * qi;
        float vA0 = od[nf][0] * inv0, vA1 = od[nf][1] * inv0;
        float vB0 = od[nf][2] * inv1, vB1 = od[nf][3] * inv1;
        if (ph == 0) {
            *(__half2*)&P1g[(size_t)hA * DD + d] = __floats2half2_rn(vA0, vA1);
            *(__half2*)&P1g[(size_t)hB * DD + d] = __floats2half2_rn(vB0, vB1);
        }
        if (hA < HO)
            *(float2*)&out[((size_t)(nbt * HO + hA) * FB + f) * DD + d] =
                make_float2(tanhf(vA0), tanhf(vA1));
        if (hB < HO)
            *(float2*)&out[((size_t)(nbt * HO + hB) * FB + f) * DD + d] =
                make_float2(tanhf(vB0), tanhf(vB1));
    }
}

// ---------------------------------------------------------------------------
extern "C" void kernel_launch(void* const* d_in, const int* in_sizes, int n_in,
                              void* d_out, int out_size)
{
    const float* prot1 = (const float*)d_in[0];
    const float* prot2 = (const float*)d_in[1];
    const float* W     = (const float*)d_in[2];
    float* out = (float*)d_out;

    proj_kernel<<<dim3(16, FB, 2 * NB), 256>>>(prot1, prot2, W);
    fused_kernel<<<dim3(8, NSLICE), 256>>>(out, 0);
    fused_kernel<<<dim3(8, NSLICE), 256>>>(out + (size_t)NB * HO * FB * DD, 1);
}

// round 15
// speedup vs baseline: 2.9736x; 1.0981x over previous
#include <cuda_runtime.h>
#include <cuda_fp16.h>
#include <math.h>

#define NB 4
#define FB 32
#define HIN 1024
#define CIN 8
#define DD 64
#define WW 7
#define HO 1018
#define HP 1024
#define NSLICE (NB*FB)
#define FPB 4          // filters per proj CTA

// fp16 scratch (zero-initialized; padded rows of q1/q2 never written -> stay 0)
__device__ __half g_q1h[(size_t)NSLICE * HP * DD];
__device__ __half g_q2h[(size_t)NSLICE * HP * DD];
__device__ __half g_p1h[(size_t)NSLICE * HP * DD];

// ---------------------------------------------------------------------------
// helpers
// ---------------------------------------------------------------------------
__device__ __forceinline__ void mma16(float* d, const unsigned* a, unsigned b0, unsigned b1) {
    asm volatile(
        "mma.sync.aligned.m16n8k16.row.col.f32.f16.f16.f32 "
        "{%0,%1,%2,%3},{%4,%5,%6,%7},{%8,%9},{%0,%1,%2,%3};"
        : "+f"(d[0]), "+f"(d[1]), "+f"(d[2]), "+f"(d[3])
        : "r"(a[0]), "r"(a[1]), "r"(a[2]), "r"(a[3]), "r"(b0), "r"(b1));
}

__device__ __forceinline__ void ldsm4(unsigned* r, const void* p) {
    unsigned a = (unsigned)__cvta_generic_to_shared(p);
    asm volatile("ldmatrix.sync.aligned.m8n8.x4.shared.b16 {%0,%1,%2,%3},[%4];"
                 : "=r"(r[0]), "=r"(r[1]), "=r"(r[2]), "=r"(r[3]) : "r"(a));
}

__device__ __forceinline__ void ldsm4t(unsigned* r, const void* p) {
    unsigned a = (unsigned)__cvta_generic_to_shared(p);
    asm volatile("ldmatrix.sync.aligned.m8n8.x4.trans.shared.b16 {%0,%1,%2,%3},[%4];"
                 : "=r"(r[0]), "=r"(r[1]), "=r"(r[2]), "=r"(r[3]) : "r"(a));
}

__device__ __forceinline__ void cpa16(void* s, const void* g) {
    unsigned sa = (unsigned)__cvta_generic_to_shared(s);
    asm volatile("cp.async.cg.shared.global [%0],[%1],16;" :: "r"(sa), "l"(g));
}
#define CP_COMMIT asm volatile("cp.async.commit_group;")
#define CP_WAIT0  asm volatile("cp.async.wait_group 0;")
#define CP_WAIT1  asm volatile("cp.async.wait_group 1;")

__device__ __forceinline__ unsigned h2u(float x, float y) {
    __half2 h = __float22half2_rn(make_float2(x, y));
    return *(unsigned*)&h;
}

// XOR swizzle for 128B rows of 64 halves: 16B unit u (0..7), phys = u ^ (row&7)
__device__ __forceinline__ int swz(int row, int u) {
    return row * 64 + ((u ^ (row & 7)) << 3);
}

// ---------------------------------------------------------------------------
// Projection v3: x window in registers reused across FPB filters.
// Thread = (h-block of 8 rows) x (d-pair). CTA 256 thr = 8 hblk x 32 dpair
// -> 64 h rows x 64 d for FPB filters. grid (16, FB/FPB, 2N).
// W smem layout: [fl][j][c][d] so the inner LDS.64 is d-contiguous.
// ---------------------------------------------------------------------------
#define PROJ_SMEM (FPB * WW * CIN * DD * 4)

__global__ __launch_bounds__(256) void proj_kernel(const float* __restrict__ x1,
                                                   const float* __restrict__ x2,
                                                   const float* __restrict__ W)
{
    extern __shared__ float Wt[];   // [FPB][WW][CIN][DD]
    const int f0 = blockIdx.y * FPB;
    const int which = blockIdx.z & 1, n = blockIdx.z >> 1;
    const float* Wf = W + (size_t)f0 * CIN * DD * WW;
    for (int i = threadIdx.x; i < FPB * CIN * DD * WW; i += 256) {
        int fl = i / (CIN * DD * WW), i2 = i % (CIN * DD * WW);
        int c = i2 / (DD * WW), rem = i2 - c * DD * WW;
        int d = rem / WW, j = rem - d * WW;
        Wt[((fl * WW + j) * CIN + c) * DD + d] = Wf[i];
    }
    __syncthreads();

    const float* x = which ? x2 : x1;
    __half* q = which ? g_q2h : g_q1h;

    const int tid = threadIdx.x;
    const int d = (tid & 31) * 2;
    const int hb = tid >> 5;
    const int h0 = blockIdx.x * 64 + hb * 8;

    unsigned long long acc[FPB][8] = {};   // f32x2; 0 bits == (0.f,0.f)

#pragma unroll
    for (int c = 0; c < CIN; c++) {
        unsigned long long xc[14];
#pragma unroll
        for (int i = 0; i < 14; i++) {
            int hr = h0 + i;
            hr = hr < HIN ? hr : HIN - 1;   // clamp; those outputs are discarded
            xc[i] = *(const unsigned long long*)
                        (x + ((size_t)(n * HIN + hr) * CIN + c) * DD + d);
        }
#pragma unroll
        for (int j = 0; j < WW; j++) {
#pragma unroll
            for (int fl = 0; fl < FPB; fl++) {
                float2 wv = *(const float2*)&Wt[((fl * WW + j) * CIN + c) * DD + d];
                unsigned long long w01;
                asm("mov.b64 %0, {%1, %2};" : "=l"(w01) : "f"(wv.x), "f"(wv.y));
#pragma unroll
                for (int i = 0; i < 8; i++)
                    asm("fma.rn.f32x2 %0, %1, %2, %0;"
                        : "+l"(acc[fl][i]) : "l"(xc[i + j]), "l"(w01));
            }
        }
    }

#pragma unroll
    for (int fl = 0; fl < FPB; fl++) {
        __half* qb = q + ((size_t)(n * FB + f0 + fl) * HP) * DD + d;
#pragma unroll
        for (int i = 0; i < 8; i++) {
            int h = h0 + i;
            if (h < HO) {
                float a0, a1;
                asm("mov.b64 {%0, %1}, %2;" : "=f"(a0), "=f"(a1) : "l"(acc[fl][i]));
                *(__half2*)(qb + (size_t)h * DD) = __floats2half2_rn(a0, a1);
            }
        }
    }
}

// ---------------------------------------------------------------------------
// Fused pass, m-split (reduction-free). CTA = 128 h-rows, 8 warps x 16 rows.
// Loop over g in 16 blocks of 64; no max-shift => pure accumulation.
// grid (8 h-blocks, 128 slices), 256 threads, 2 CTAs/SM. (unchanged)
// ---------------------------------------------------------------------------
__global__ __launch_bounds__(256, 2) void fused_kernel(float* __restrict__ out, int ph)
{
    __shared__ __align__(16) __half Q1s[128 * 64];
    __shared__ __align__(16) __half Ks[2 * 64 * 64];
    __shared__ __align__(16) __half Vs[2 * 64 * 64];

    const int slice = blockIdx.y;
    const int m0 = blockIdx.x * 128;
    const int tid = threadIdx.x;
    const int wid = tid >> 5, lane = tid & 31;
    const int gq = lane >> 2, qi = lane & 3;
    const int nbt = slice >> 5, f = slice & 31;

    const __half* Kg  = g_q2h + (size_t)slice * HP * DD;
    const __half* Vg  = (ph ? g_p1h : g_q2h) + (size_t)slice * HP * DD;
    const __half* Q1g = g_q1h + ((size_t)slice * HP + m0) * DD;
    __half*       P1g = g_p1h + (size_t)slice * HP * DD;

    // ---- prologue: G0 = Q1 + tile0, G1 = tile1
    {
#pragma unroll
        for (int r = 0; r < 4; r++) {
            int op = tid + r * 256, row = op >> 3, u = op & 7;
            cpa16(Q1s + swz(row, u), Q1g + (size_t)row * 64 + u * 8);
        }
#pragma unroll
        for (int r = 0; r < 2; r++) {
            int op = tid + r * 256, row = op >> 3, u = op & 7;
            cpa16(Ks + swz(row, u), Kg + (size_t)row * 64 + u * 8);
            if (ph) cpa16(Vs + swz(row, u), Vg + (size_t)row * 64 + u * 8);
        }
        CP_COMMIT;
#pragma unroll
        for (int r = 0; r < 2; r++) {
            int op = tid + r * 256, row = op >> 3, u = op & 7;
            cpa16(Ks + 4096 + swz(row, u), Kg + (size_t)(64 + row) * 64 + u * 8);
            if (ph) cpa16(Vs + 4096 + swz(row, u), Vg + (size_t)(64 + row) * 64 + u * 8);
        }
        CP_COMMIT;
    }

    CP_WAIT1; __syncthreads();
    unsigned afr[4][4];
#pragma unroll
    for (int ks = 0; ks < 4; ks++)
        ldsm4(afr[ks], Q1s + swz(wid * 16 + (lane & 15), ks * 2 + (lane >> 4)));

    const float sc = 1.0f / 1018.0f;
    float od[8][4] = {};
    float l0 = 0.f, l1 = 0.f;

#pragma unroll 1
    for (int kb = 0; kb < 16; kb++) {
        if (kb) { CP_WAIT1; __syncthreads(); }
        const __half* Kt = Ks + (kb & 1) * 4096;
        const __half* Vt = ph ? (Vs + (kb & 1) * 4096) : Kt;

        float acc[8][4] = {};
#pragma unroll
        for (int nb = 0; nb < 4; nb++) {
            unsigned bb[4][4];
#pragma unroll
            for (int ks = 0; ks < 4; ks++)
                ldsm4(bb[ks], Kt + swz(nb * 16 + (lane & 15), ks * 2 + (lane >> 4)));
#pragma unroll
            for (int ks = 0; ks < 4; ks++) {
                mma16(acc[nb * 2],     afr[ks], bb[ks][0], bb[ks][2]);
                mma16(acc[nb * 2 + 1], afr[ks], bb[ks][1], bb[ks][3]);
            }
        }

        if (kb < 15) {
#pragma unroll
            for (int j = 0; j < 8; j++) {
                acc[j][0] = __expf(acc[j][0] * sc);
                acc[j][1] = __expf(acc[j][1] * sc);
                acc[j][2] = __expf(acc[j][2] * sc);
                acc[j][3] = __expf(acc[j][3] * sc);
                l0 += acc[j][0] + acc[j][1];
                l1 += acc[j][2] + acc[j][3];
            }
        } else {
#pragma unroll
            for (int j = 0; j < 8; j++) {
                int gcol = kb * 64 + (j >> 1) * 16 + (j & 1) * 8 + 2 * qi;
                acc[j][0] = (gcol < HO)     ? __expf(acc[j][0] * sc) : 0.f;
                acc[j][1] = (gcol + 1 < HO) ? __expf(acc[j][1] * sc) : 0.f;
                acc[j][2] = (gcol < HO)     ? __expf(acc[j][2] * sc) : 0.f;
                acc[j][3] = (gcol + 1 < HO) ? __expf(acc[j][3] * sc) : 0.f;
                l0 += acc[j][0] + acc[j][1];
                l1 += acc[j][2] + acc[j][3];
            }
        }

#pragma unroll
        for (int kg = 0; kg < 4; kg++) {
            unsigned a[4];
            a[0] = h2u(acc[kg * 2][0],     acc[kg * 2][1]);
            a[1] = h2u(acc[kg * 2][2],     acc[kg * 2][3]);
            a[2] = h2u(acc[kg * 2 + 1][0], acc[kg * 2 + 1][1]);
            a[3] = h2u(acc[kg * 2 + 1][2], acc[kg * 2 + 1][3]);
#pragma unroll
            for (int dv = 0; dv < 4; dv++) {
                unsigned bb[4];
                ldsm4t(bb, Vt + swz(kg * 16 + (lane & 15), dv * 2 + (lane >> 4)));
                mma16(od[dv * 2],     a, bb[0], bb[1]);
                mma16(od[dv * 2 + 1], a, bb[2], bb[3]);
            }
        }

        __syncthreads();
        if (kb + 2 < 16) {
            int slot = kb & 1, g0 = (kb + 2) * 64;
#pragma unroll
            for (int r = 0; r < 2; r++) {
                int op = tid + r * 256, row = op >> 3, u = op & 7;
                cpa16(Ks + slot * 4096 + swz(row, u),
                      Kg + (size_t)(g0 + row) * 64 + u * 8);
                if (ph) cpa16(Vs + slot * 4096 + swz(row, u),
                              Vg + (size_t)(g0 + row) * 64 + u * 8);
            }
        }
        CP_COMMIT;
    }

    l0 += __shfl_xor_sync(~0u, l0, 1); l0 += __shfl_xor_sync(~0u, l0, 2);
    l1 += __shfl_xor_sync(~0u, l1, 1); l1 += __shfl_xor_sync(~0u, l1, 2);
    const float inv0 = 1.0f / l0, inv1 = 1.0f / l1;
    const int h0g = m0 + wid * 16;
    const int hA = h0g + gq, hB = h0g + gq + 8;

#pragma unroll
    for (int nf = 0; nf < 8; nf++) {
        int d = nf * 8 + 2 * qi;
        float vA0 = od[nf][0] * inv0, vA1 = od[nf][1] * inv0;
        float vB0 = od[nf][2] * inv1, vB1 = od[nf][3] * inv1;
        if (ph == 0) {
            *(__half2*)&P1g[(size_t)hA * DD + d] = __floats2half2_rn(vA0, vA1);
            *(__half2*)&P1g[(size_t)hB * DD + d] = __floats2half2_rn(vB0, vB1);
        }
        if (hA < HO)
            *(float2*)&out[((size_t)(nbt * HO + hA) * FB + f) * DD + d] =
                make_float2(tanhf(vA0), tanhf(vA1));
        if (hB < HO)
            *(float2*)&out[((size_t)(nbt * HO + hB) * FB + f) * DD + d] =
                make_float2(tanhf(vB0), tanhf(vB1));
    }
}

// ---------------------------------------------------------------------------
extern "C" void kernel_launch(void* const* d_in, const int* in_sizes, int n_in,
                              void* d_out, int out_size)
{
    const float* prot1 = (const float*)d_in[0];
    const float* prot2 = (const float*)d_in[1];
    const float* W     = (const float*)d_in[2];
    float* out = (float*)d_out;

    cudaFuncSetAttribute(proj_kernel, cudaFuncAttributeMaxDynamicSharedMemorySize,
                         PROJ_SMEM);

    proj_kernel<<<dim3(16, FB / FPB, 2 * NB), 256, PROJ_SMEM>>>(prot1, prot2, W);
    fused_kernel<<<dim3(8, NSLICE), 256>>>(out, 0);
    fused_kernel<<<dim3(8, NSLICE), 256>>>(out + (size_t)NB * HO * FB * DD, 1);
}

// round 17
// speedup vs baseline: 3.4715x; 1.1675x over previous
#include <cuda_runtime.h>
#include <cuda_fp16.h>
#include <math.h>

#define NB 4
#define FB 32
#define HIN 1024
#define CIN 8
#define DD 64
#define WW 7
#define HO 1018
#define HP 1024
#define NSLICE (NB*FB)
#define FPB 4          // filters per proj CTA

// log2(e)/1018 folded into q1 at projection time
#define K_FOLD 1.4172005e-3f

// fp16 scratch (zero-initialized; padded rows of q1/q2 never written -> stay 0)
__device__ __half g_q1h[(size_t)NSLICE * HP * DD];
__device__ __half g_q2h[(size_t)NSLICE * HP * DD];
__device__ __half g_p1h[(size_t)NSLICE * HP * DD];

// ---------------------------------------------------------------------------
// helpers
// ---------------------------------------------------------------------------
__device__ __forceinline__ void mma16(float* d, const unsigned* a, unsigned b0, unsigned b1) {
    asm volatile(
        "mma.sync.aligned.m16n8k16.row.col.f32.f16.f16.f32 "
        "{%0,%1,%2,%3},{%4,%5,%6,%7},{%8,%9},{%0,%1,%2,%3};"
        : "+f"(d[0]), "+f"(d[1]), "+f"(d[2]), "+f"(d[3])
        : "r"(a[0]), "r"(a[1]), "r"(a[2]), "r"(a[3]), "r"(b0), "r"(b1));
}

__device__ __forceinline__ void ldsm4(unsigned* r, const void* p) {
    unsigned a = (unsigned)__cvta_generic_to_shared(p);
    asm volatile("ldmatrix.sync.aligned.m8n8.x4.shared.b16 {%0,%1,%2,%3},[%4];"
                 : "=r"(r[0]), "=r"(r[1]), "=r"(r[2]), "=r"(r[3]) : "r"(a));
}

__device__ __forceinline__ void ldsm4t(unsigned* r, const void* p) {
    unsigned a = (unsigned)__cvta_generic_to_shared(p);
    asm volatile("ldmatrix.sync.aligned.m8n8.x4.trans.shared.b16 {%0,%1,%2,%3},[%4];"
                 : "=r"(r[0]), "=r"(r[1]), "=r"(r[2]), "=r"(r[3]) : "r"(a));
}

__device__ __forceinline__ void cpa16(void* s, const void* g) {
    unsigned sa = (unsigned)__cvta_generic_to_shared(s);
    asm volatile("cp.async.cg.shared.global [%0],[%1],16;" :: "r"(sa), "l"(g));
}
#define CP_COMMIT asm volatile("cp.async.commit_group;")
#define CP_WAIT0  asm volatile("cp.async.wait_group 0;")
#define CP_WAIT1  asm volatile("cp.async.wait_group 1;")

// pack (lo,hi) f32 pair -> f16x2, then exp2 in f16x2 on the MUFU
__device__ __forceinline__ unsigned exp2_pack(float lo, float hi) {
    unsigned d;
    asm("cvt.rn.f16x2.f32 %0, %2, %1;" : "=r"(d) : "f"(lo), "f"(hi));
    asm("ex2.approx.f16x2 %0, %0;" : "+r"(d));
    return d;
}

// XOR swizzle for 128B rows of 64 halves: 16B unit u (0..7), phys = u ^ (row&7)
__device__ __forceinline__ int swz(int row, int u) {
    return row * 64 + ((u ^ (row & 7)) << 3);
}

// ---------------------------------------------------------------------------
// Projection v3: x window in registers reused across FPB filters.
// q1 output is pre-scaled by K_FOLD (softmax scale folded into the S-GEMM).
// ---------------------------------------------------------------------------
#define PROJ_SMEM (FPB * WW * CIN * DD * 4)

__global__ __launch_bounds__(256) void proj_kernel(const float* __restrict__ x1,
                                                   const float* __restrict__ x2,
                                                   const float* __restrict__ W)
{
    extern __shared__ float Wt[];   // [FPB][WW][CIN][DD]
    const int f0 = blockIdx.y * FPB;
    const int which = blockIdx.z & 1, n = blockIdx.z >> 1;
    const float* Wf = W + (size_t)f0 * CIN * DD * WW;
    for (int i = threadIdx.x; i < FPB * CIN * DD * WW; i += 256) {
        int fl = i / (CIN * DD * WW), i2 = i % (CIN * DD * WW);
        int c = i2 / (DD * WW), rem = i2 - c * DD * WW;
        int d = rem / WW, j = rem - d * WW;
        Wt[((fl * WW + j) * CIN + c) * DD + d] = Wf[i];
    }
    __syncthreads();

    const float* x = which ? x2 : x1;
    __half* q = which ? g_q2h : g_q1h;
    const float kf = which ? 1.0f : K_FOLD;

    const int tid = threadIdx.x;
    const int d = (tid & 31) * 2;
    const int hb = tid >> 5;
    const int h0 = blockIdx.x * 64 + hb * 8;

    unsigned long long acc[FPB][8] = {};   // f32x2; 0 bits == (0.f,0.f)

#pragma unroll
    for (int c = 0; c < CIN; c++) {
        unsigned long long xc[14];
#pragma unroll
        for (int i = 0; i < 14; i++) {
            int hr = h0 + i;
            hr = hr < HIN ? hr : HIN - 1;   // clamp; those outputs are discarded
            xc[i] = *(const unsigned long long*)
                        (x + ((size_t)(n * HIN + hr) * CIN + c) * DD + d);
        }
#pragma unroll
        for (int j = 0; j < WW; j++) {
#pragma unroll
            for (int fl = 0; fl < FPB; fl++) {
                float2 wv = *(const float2*)&Wt[((fl * WW + j) * CIN + c) * DD + d];
                unsigned long long w01;
                asm("mov.b64 %0, {%1, %2};" : "=l"(w01) : "f"(wv.x), "f"(wv.y));
#pragma unroll
                for (int i = 0; i < 8; i++)
                    asm("fma.rn.f32x2 %0, %1, %2, %0;"
                        : "+l"(acc[fl][i]) : "l"(xc[i + j]), "l"(w01));
            }
        }
    }

#pragma unroll
    for (int fl = 0; fl < FPB; fl++) {
        __half* qb = q + ((size_t)(n * FB + f0 + fl) * HP) * DD + d;
#pragma unroll
        for (int i = 0; i < 8; i++) {
            int h = h0 + i;
            if (h < HO) {
                float a0, a1;
                asm("mov.b64 {%0, %1}, %2;" : "=f"(a0), "=f"(a1) : "l"(acc[fl][i]));
                *(__half2*)(qb + (size_t)h * DD) =
                    __floats2half2_rn(a0 * kf, a1 * kf);
            }
        }
    }
}

// ---------------------------------------------------------------------------
// Fused pass, m-split (reduction-free). CTA = 128 h-rows, 8 warps x 16 rows.
// S-GEMM output = exp2 argument (scale folded into q1). exp via
// ex2.approx.f16x2 -> directly the fp16x2 A-fragments for the O-GEMM.
// l computed on the tensor pipe (extra MMA against an all-ones B fragment).
// grid (8 h-blocks, 128 slices), 256 threads, 2 CTAs/SM.
// ---------------------------------------------------------------------------
#define ONESF16X2 0x3C003C00u

__global__ __launch_bounds__(256, 2) void fused_kernel(float* __restrict__ out, int ph)
{
    __shared__ __align__(16) __half Q1s[128 * 64];
    __shared__ __align__(16) __half Ks[2 * 64 * 64];
    __shared__ __align__(16) __half Vs[2 * 64 * 64];

    const int slice = blockIdx.y;
    const int m0 = blockIdx.x * 128;
    const int tid = threadIdx.x;
    const int wid = tid >> 5, lane = tid & 31;
    const int gq = lane >> 2, qi = lane & 3;
    const int nbt = slice >> 5, f = slice & 31;

    const __half* Kg  = g_q2h + (size_t)slice * HP * DD;
    const __half* Vg  = (ph ? g_p1h : g_q2h) + (size_t)slice * HP * DD;
    const __half* Q1g = g_q1h + ((size_t)slice * HP + m0) * DD;
    __half*       P1g = g_p1h + (size_t)slice * HP * DD;

    // ---- prologue: G0 = Q1 + tile0, G1 = tile1
    {
#pragma unroll
        for (int r = 0; r < 4; r++) {
            int op = tid + r * 256, row = op >> 3, u = op & 7;
            cpa16(Q1s + swz(row, u), Q1g + (size_t)row * 64 + u * 8);
        }
#pragma unroll
        for (int r = 0; r < 2; r++) {
            int op = tid + r * 256, row = op >> 3, u = op & 7;
            cpa16(Ks + swz(row, u), Kg + (size_t)row * 64 + u * 8);
            if (ph) cpa16(Vs + swz(row, u), Vg + (size_t)row * 64 + u * 8);
        }
        CP_COMMIT;
#pragma unroll
        for (int r = 0; r < 2; r++) {
            int op = tid + r * 256, row = op >> 3, u = op & 7;
            cpa16(Ks + 4096 + swz(row, u), Kg + (size_t)(64 + row) * 64 + u * 8);
            if (ph) cpa16(Vs + 4096 + swz(row, u), Vg + (size_t)(64 + row) * 64 + u * 8);
        }
        CP_COMMIT;
    }

    CP_WAIT1; __syncthreads();
    unsigned afr[4][4];
#pragma unroll
    for (int ks = 0; ks < 4; ks++)
        ldsm4(afr[ks], Q1s + swz(wid * 16 + (lane & 15), ks * 2 + (lane >> 4)));

    float od[8][4] = {};
    float lacc[4] = {};

#pragma unroll 1
    for (int kb = 0; kb < 16; kb++) {
        if (kb) { CP_WAIT1; __syncthreads(); }
        const __half* Kt = Ks + (kb & 1) * 4096;
        const __half* Vt = ph ? (Vs + (kb & 1) * 4096) : Kt;

        // ---- S-frags (exp2 args): 16 rows x 64 g-cols of this block
        float acc[8][4] = {};
#pragma unroll
        for (int nb = 0; nb < 4; nb++) {
            unsigned bb[4][4];
#pragma unroll
            for (int ks = 0; ks < 4; ks++)
                ldsm4(bb[ks], Kt + swz(nb * 16 + (lane & 15), ks * 2 + (lane >> 4)));
#pragma unroll
            for (int ks = 0; ks < 4; ks++) {
                mma16(acc[nb * 2],     afr[ks], bb[ks][0], bb[ks][2]);
                mma16(acc[nb * 2 + 1], afr[ks], bb[ks][1], bb[ks][3]);
            }
        }

        // ---- P = 2^acc in f16x2 (packed == O-GEMM A fragments)
        unsigned pA[8], pB[8];
        if (kb == 15) {
#pragma unroll
            for (int j = 0; j < 8; j++) {
                int gcol = kb * 64 + (j >> 1) * 16 + (j & 1) * 8 + 2 * qi;
                if (gcol >= HO)     { acc[j][0] = -1e4f; acc[j][2] = -1e4f; }
                if (gcol + 1 >= HO) { acc[j][1] = -1e4f; acc[j][3] = -1e4f; }
            }
        }
#pragma unroll
        for (int j = 0; j < 8; j++) {
            pA[j] = exp2_pack(acc[j][0], acc[j][1]);
            pB[j] = exp2_pack(acc[j][2], acc[j][3]);
        }

        // ---- O += P * V ; l += P * 1 (tensor pipe)
#pragma unroll
        for (int kg = 0; kg < 4; kg++) {
            unsigned a[4];
            a[0] = pA[kg * 2];     a[1] = pB[kg * 2];
            a[2] = pA[kg * 2 + 1]; a[3] = pB[kg * 2 + 1];
            mma16(lacc, a, ONESF16X2, ONESF16X2);
#pragma unroll
            for (int dv = 0; dv < 4; dv++) {
                unsigned bb[4];
                ldsm4t(bb, Vt + swz(kg * 16 + (lane & 15), dv * 2 + (lane >> 4)));
                mma16(od[dv * 2],     a, bb[0], bb[1]);
                mma16(od[dv * 2 + 1], a, bb[2], bb[3]);
            }
        }

        __syncthreads();
        if (kb + 2 < 16) {
            int slot = kb & 1, g0 = (kb + 2) * 64;
#pragma unroll
            for (int r = 0; r < 2; r++) {
                int op = tid + r * 256, row = op >> 3, u = op & 7;
                cpa16(Ks + slot * 4096 + swz(row, u),
                      Kg + (size_t)(g0 + row) * 64 + u * 8);
                if (ph) cpa16(Vs + slot * 4096 + swz(row, u),
                              Vg + (size_t)(g0 + row) * 64 + u * 8);
            }
        }
        CP_COMMIT;
    }

    // ---- epilogue: lacc[0]/lacc[2] ARE the row sums (ones-B => all cols equal)
    const float inv0 = 1.0f / lacc[0], inv1 = 1.0f / lacc[2];
    const int h0g = m0 + wid * 16;
    const int hA = h0g + gq, hB = h0g + gq + 8;

#pragma unroll
    for (int nf = 0; nf < 8; nf++) {
        int d = nf * 8 + 2 * qi;
        float vA0 = od[nf][0] * inv0, vA1 = od[nf][1] * inv0;
        float vB0 = od[nf][2] * inv1, vB1 = od[nf][3] * inv1;
        if (ph == 0) {
            *(__half2*)&P1g[(size_t)hA * DD + d] = __floats2half2_rn(vA0, vA1);
            *(__half2*)&P1g[(size_t)hB * DD + d] = __floats2half2_rn(vB0, vB1);
        }
        if (hA < HO)
            *(float2*)&out[((size_t)(nbt * HO + hA) * FB + f) * DD + d] =
                make_float2(tanhf(vA0), tanhf(vA1));
        if (hB < HO)
            *(float2*)&out[((size_t)(nbt * HO + hB) * FB + f) * DD + d] =
                make_float2(tanhf(vB0), tanhf(vB1));
    }
}

// ---------------------------------------------------------------------------
extern "C" void kernel_launch(void* const* d_in, const int* in_sizes, int n_in,
                              void* d_out, int out_size)
{
    const float* prot1 = (const float*)d_in[0];
    const float* prot2 = (const float*)d_in[1];
    const float* W     = (const float*)d_in[2];
    float* out = (float*)d_out;

    cudaFuncSetAttribute(proj_kernel, cudaFuncAttributeMaxDynamicSharedMemorySize,
                         PROJ_SMEM);

    proj_kernel<<<dim3(16, FB / FPB, 2 * NB), 256, PROJ_SMEM>>>(prot1, prot2, W);
    fused_kernel<<<dim3(8, NSLICE), 256>>>(out, 0);
    fused_kernel<<<dim3(8, NSLICE), 256>>>(out + (size_t)NB * HO * FB * DD, 1);
}